// round 3
// baseline (speedup 1.0000x reference)
#include <cuda_runtime.h>

#define BATCH 2
#define LSEQ  16384
#define BLR   (BATCH*LSEQ)   // 32768 rows
#define DM    60
#define DI    120
#define DS    16
#define NCH   64             // scan chunks
#define SCH   (LSEQ/NCH)     // 256 steps per chunk

// ------------------------- scratch (static device globals) -------------------------
__device__ float g_hn[BLR*DM];
__device__ float g_xz[BLR*2*DI];
__device__ float g_xc[BLR*DI];
__device__ float g_xdb[BLR*36];
__device__ float g_delta[BLR*DI];
__device__ float g_u[BLR*DI];
__device__ float g_y[BLR*DI];
__device__ float g_h[BLR*DM];
__device__ float g_wT[9*60*60];
__device__ float g_P [NCH*BATCH*DI*DS];
__device__ float g_Hc[NCH*BATCH*DI*DS];
__device__ float g_hinit[NCH*BATCH*DI*DS];

__device__ __forceinline__ float siluf(float x) { return x / (1.f + __expf(-x)); }

// ------------------------- LayerNorm (one warp per row) -------------------------
__global__ void ln_kernel(const float* __restrict__ in, const float* __restrict__ w,
                          const float* __restrict__ b) {
    int row  = blockIdx.x * 8 + (threadIdx.x >> 5);
    int lane = threadIdx.x & 31;
    const float* r = in + (size_t)row * DM;
    float v0 = r[lane];
    float v1 = (lane + 32 < DM) ? r[lane + 32] : 0.f;
    float s = v0 + v1;
#pragma unroll
    for (int o = 16; o; o >>= 1) s += __shfl_xor_sync(0xffffffffu, s, o);
    float mu = s * (1.f / DM);
    float d0 = v0 - mu;
    float d1 = (lane + 32 < DM) ? (v1 - mu) : 0.f;
    float q = d0 * d0 + d1 * d1;
#pragma unroll
    for (int o = 16; o; o >>= 1) q += __shfl_xor_sync(0xffffffffu, q, o);
    float rstd = rsqrtf(q * (1.f / DM) + 1e-5f);
    float* op = g_hn + (size_t)row * DM;
    op[lane] = d0 * rstd * w[lane] + b[lane];
    if (lane + 32 < DM) op[lane + 32] = d1 * rstd * w[lane + 32] + b[lane + 32];
}

// ------------------------- generic GEMM: C[m,n] = sum_k A[m,k]*W[n,k] -------------------------
// BM=64 rows, BN=64 cols per block, K in {60,120} (chunks of 60), 256 threads, 4x4 microtile
__global__ void gemm64(const float* __restrict__ A, const float* __restrict__ W,
                       float* __restrict__ C, int N, int K) {
    __shared__ float As[60][64];
    __shared__ float Ws[60][64];
    int m0 = blockIdx.x * 64;
    int n0 = blockIdx.y * 64;
    int tid = threadIdx.x;
    int r0 = (tid >> 4) * 4;
    int c0 = (tid & 15) * 4;
    float acc[4][4];
#pragma unroll
    for (int i = 0; i < 4; i++)
#pragma unroll
        for (int j = 0; j < 4; j++) acc[i][j] = 0.f;

    for (int kc = 0; kc < K; kc += 60) {
        for (int i = tid; i < 64 * 60; i += 256) {
            int r = i / 60, k = i - r * 60;
            As[k][r] = A[(size_t)(m0 + r) * K + kc + k];
        }
        for (int i = tid; i < 64 * 60; i += 256) {
            int n = i / 60, k = i - n * 60;
            Ws[k][n] = (n0 + n < N) ? W[(size_t)(n0 + n) * K + kc + k] : 0.f;
        }
        __syncthreads();
#pragma unroll
        for (int k = 0; k < 60; k++) {
            float4 a = *(const float4*)&As[k][r0];
            float4 wv = *(const float4*)&Ws[k][c0];
            float av[4] = {a.x, a.y, a.z, a.w};
            float bv[4] = {wv.x, wv.y, wv.z, wv.w};
#pragma unroll
            for (int i = 0; i < 4; i++)
#pragma unroll
                for (int j = 0; j < 4; j++) acc[i][j] = fmaf(av[i], bv[j], acc[i][j]);
        }
        __syncthreads();
    }
#pragma unroll
    for (int i = 0; i < 4; i++) {
        int m = m0 + r0 + i;
#pragma unroll
        for (int j = 0; j < 4; j++) {
            int n = n0 + c0 + j;
            if (n < N) C[(size_t)m * N + n] = acc[i][j];
        }
    }
}

// ------------------------- causal depthwise conv1d (k=4) + bias + SiLU -------------------------
__global__ void conv1d_silu(const float* __restrict__ cw, const float* __restrict__ cb) {
    int idx = blockIdx.x * 256 + threadIdx.x;
    if (idx >= BLR * DI) return;
    int m = idx / DI;
    int d = idx - m * DI;
    int l = m & (LSEQ - 1);
    const float* base = g_xz + (size_t)m * (2 * DI) + d;  // xin = first DI cols of xz
    const float* w = cw + d * 4;
    float acc = cb[d] + base[0] * w[3];
    if (l >= 1) acc = fmaf(base[-(2 * DI)], w[2], acc);
    if (l >= 2) acc = fmaf(base[-2 * (2 * DI)], w[1], acc);
    if (l >= 3) acc = fmaf(base[-3 * (2 * DI)], w[0], acc);
    g_xc[idx] = siluf(acc);
}

// ------------------------- delta = softplus(dt @ dtw^T + dtb); u = delta*xc -------------------------
__global__ void delta_kernel(const float* __restrict__ dtw, const float* __restrict__ dtb) {
    int idx = blockIdx.x * 256 + threadIdx.x;
    if (idx >= BLR * DI) return;
    int m = idx / DI;
    int d = idx - m * DI;
    const float* xr = g_xdb + (size_t)m * 36;
    const float* wr = dtw + d * 4;
    float s = dtb[d];
    s = fmaf(xr[0], wr[0], s);
    s = fmaf(xr[1], wr[1], s);
    s = fmaf(xr[2], wr[2], s);
    s = fmaf(xr[3], wr[3], s);
    float sp = (s > 20.f) ? s : log1pf(__expf(s));
    g_delta[idx] = sp;
    g_u[idx] = sp * g_xc[idx];
}

// ------------------------- chunked selective scan -------------------------
// phase 1: per chunk, compute P = prod(dA) and H = local scan result (h0=0)
__global__ void scan_phase1(const float* __restrict__ A_log) {
    int lane = threadIdx.x;
    int g = blockIdx.x;          // 0..119 : (b, d-pair)
    int c = blockIdx.y;          // chunk
    int b = g / 60;
    int d = (g % 60) * 2 + (lane >> 4);
    int n = lane & 15;
    float An = -__expf(A_log[d * DS + n]);
    const float* dp = g_delta + (size_t)b * LSEQ * DI + d;
    const float* up = g_u + (size_t)b * LSEQ * DI + d;
    const float* bp = g_xdb + (size_t)b * LSEQ * 36 + 4 + n;
    int t0 = c * SCH;
    float h = 0.f, P = 1.f;
#pragma unroll 8
    for (int t = t0; t < t0 + SCH; t++) {
        float delta = __ldg(dp + (size_t)t * DI);
        float u = __ldg(up + (size_t)t * DI);
        float Bn = __ldg(bp + (size_t)t * 36);
        float dA = __expf(delta * An);
        h = fmaf(dA, h, u * Bn);
        P *= dA;
    }
    int o = ((c * BATCH + b) * DI + d) * DS + n;
    g_Hc[o] = h;
    g_P[o] = P;
}

// phase 2: exclusive prefix over chunks per (b,d,n)
__global__ void scan_phase2() {
    int tid = blockIdx.x * 256 + threadIdx.x;
    if (tid >= BATCH * DI * DS) return;
    float h = 0.f;
    for (int c = 0; c < NCH; c++) {
        int o = c * (BATCH * DI * DS) + tid;
        g_hinit[o] = h;
        h = fmaf(g_P[o], h, g_Hc[o]);
    }
}

// phase 3: replay chunk with correct h_init, emit y[t,d] = sum_n h*C
__global__ void scan_phase3(const float* __restrict__ A_log) {
    int lane = threadIdx.x;
    int g = blockIdx.x;
    int c = blockIdx.y;
    int b = g / 60;
    int d = (g % 60) * 2 + (lane >> 4);
    int n = lane & 15;
    float An = -__expf(A_log[d * DS + n]);
    const float* dp = g_delta + (size_t)b * LSEQ * DI + d;
    const float* up = g_u + (size_t)b * LSEQ * DI + d;
    const float* bp = g_xdb + (size_t)b * LSEQ * 36 + 4 + n;
    const float* cp = g_xdb + (size_t)b * LSEQ * 36 + 20 + n;
    float* yp = g_y + (size_t)b * LSEQ * DI + d;
    int t0 = c * SCH;
    float h = g_hinit[((c * BATCH + b) * DI + d) * DS + n];
#pragma unroll 8
    for (int t = t0; t < t0 + SCH; t++) {
        float delta = __ldg(dp + (size_t)t * DI);
        float u = __ldg(up + (size_t)t * DI);
        float Bn = __ldg(bp + (size_t)t * 36);
        float Cn = __ldg(cp + (size_t)t * 36);
        float dA = __expf(delta * An);
        h = fmaf(dA, h, u * Bn);
        float s = h * Cn;
        s += __shfl_xor_sync(0xffffffffu, s, 1);
        s += __shfl_xor_sync(0xffffffffu, s, 2);
        s += __shfl_xor_sync(0xffffffffu, s, 4);
        s += __shfl_xor_sync(0xffffffffu, s, 8);
        if (n == 0) yp[(size_t)t * DI] = s;
    }
}

// ------------------------- out_proj with fused gating: A = (y + D*xc)*silu(z) -------------------------
__global__ void gemm_out_gated(const float* __restrict__ Wo, const float* __restrict__ Dvec) {
    __shared__ float As[60][64];
    __shared__ float Ws[60][64];
    int m0 = blockIdx.x * 64;
    int tid = threadIdx.x;
    int r0 = (tid >> 4) * 4;
    int c0 = (tid & 15) * 4;
    float acc[4][4];
#pragma unroll
    for (int i = 0; i < 4; i++)
#pragma unroll
        for (int j = 0; j < 4; j++) acc[i][j] = 0.f;

    for (int kc = 0; kc < DI; kc += 60) {
        for (int i = tid; i < 64 * 60; i += 256) {
            int r = i / 60, k = i - r * 60;
            int m = m0 + r;
            int e = kc + k;
            float yv = g_y[(size_t)m * DI + e];
            float xcv = g_xc[(size_t)m * DI + e];
            float zv = g_xz[(size_t)m * (2 * DI) + DI + e];
            As[k][r] = (yv + Dvec[e] * xcv) * siluf(zv);
        }
        for (int i = tid; i < 64 * 60; i += 256) {
            int n = i / 60, k = i - n * 60;
            Ws[k][n] = (n < DM) ? Wo[(size_t)n * DI + kc + k] : 0.f;
        }
        __syncthreads();
#pragma unroll
        for (int k = 0; k < 60; k++) {
            float4 a = *(const float4*)&As[k][r0];
            float4 wv = *(const float4*)&Ws[k][c0];
            float av[4] = {a.x, a.y, a.z, a.w};
            float bv[4] = {wv.x, wv.y, wv.z, wv.w};
#pragma unroll
            for (int i = 0; i < 4; i++)
#pragma unroll
                for (int j = 0; j < 4; j++) acc[i][j] = fmaf(av[i], bv[j], acc[i][j]);
        }
        __syncthreads();
    }
#pragma unroll
    for (int i = 0; i < 4; i++) {
        int m = m0 + r0 + i;
#pragma unroll
        for (int j = 0; j < 4; j++) {
            int n = c0 + j;
            if (n < DM) g_h[(size_t)m * DM + n] = acc[i][j];
        }
    }
}

// ------------------------- conv2d weight transpose: [co][ci][9] -> [tap][ci][co] -------------------------
__global__ void wconv_T(const float* __restrict__ w) {
    int i = blockIdx.x * 256 + threadIdx.x;
    if (i >= 9 * 60 * 60) return;
    int tap = i / 3600;
    int r = i - tap * 3600;
    int ci = r / 60;
    int co = r - ci * 60;
    g_wT[i] = w[(co * 60 + ci) * 9 + tap];
}

// ------------------------- 3x3 conv2d (implicit GEMM, 9 taps) + bias + residual -------------------------
__global__ void conv2d_res(const float* __restrict__ bias, const float* __restrict__ x0,
                           float* __restrict__ outp) {
    __shared__ float As[60][64];
    __shared__ float Ws[60][64];
    int p0 = blockIdx.x * 64;
    int tid = threadIdx.x;
    int r0 = (tid >> 4) * 4;
    int c0 = (tid & 15) * 4;
    float acc[4][4];
#pragma unroll
    for (int i = 0; i < 4; i++)
#pragma unroll
        for (int j = 0; j < 4; j++) acc[i][j] = 0.f;

    for (int tap = 0; tap < 9; tap++) {
        int dy = tap / 3 - 1, dx = tap % 3 - 1;
        for (int i = tid; i < 64 * 60; i += 256) {
            int r = i / 60, ci = i - r * 60;
            int p = p0 + r;
            int l = p & (LSEQ - 1);
            int bI = p >> 14;
            int yy = l >> 7, xx = l & 127;
            int sy = yy + dy, sx = xx + dx;
            float v = 0.f;
            if ((unsigned)sy < 128u && (unsigned)sx < 128u)
                v = g_h[(size_t)((bI << 14) + (sy << 7) + sx) * DM + ci];
            As[ci][r] = v;
        }
        for (int i = tid; i < 60 * 64; i += 256) {
            int k = i >> 6, nn = i & 63;
            Ws[k][nn] = (nn < DM) ? g_wT[tap * 3600 + k * 60 + nn] : 0.f;
        }
        __syncthreads();
#pragma unroll
        for (int k = 0; k < 60; k++) {
            float4 a = *(const float4*)&As[k][r0];
            float4 wv = *(const float4*)&Ws[k][c0];
            float av[4] = {a.x, a.y, a.z, a.w};
            float bv[4] = {wv.x, wv.y, wv.z, wv.w};
#pragma unroll
            for (int i = 0; i < 4; i++)
#pragma unroll
                for (int j = 0; j < 4; j++) acc[i][j] = fmaf(av[i], bv[j], acc[i][j]);
        }
        __syncthreads();
    }
#pragma unroll
    for (int i = 0; i < 4; i++) {
        int p = p0 + r0 + i;
#pragma unroll
        for (int j = 0; j < 4; j++) {
            int co = c0 + j;
            if (co < DM)
                outp[(size_t)p * DM + co] = acc[i][j] + bias[co] + x0[(size_t)p * DM + co];
        }
    }
}

// ------------------------- launch -------------------------
extern "C" void kernel_launch(void* const* d_in, const int* in_sizes, int n_in,
                              void* d_out, int out_size) {
    (void)in_sizes; (void)n_in; (void)out_size;
    const float* x         = (const float*)d_in[0];
    const float* ln_w      = (const float*)d_in[1];
    const float* ln_b      = (const float*)d_in[2];
    const float* in_proj_w = (const float*)d_in[3];
    const float* conv_w    = (const float*)d_in[4];
    const float* conv_b    = (const float*)d_in[5];
    const float* x_proj_w  = (const float*)d_in[6];
    const float* dt_proj_w = (const float*)d_in[7];
    const float* dt_proj_b = (const float*)d_in[8];
    const float* A_log     = (const float*)d_in[9];
    const float* Dv        = (const float*)d_in[10];
    const float* out_proj_w= (const float*)d_in[11];
    const float* conv2d_w  = (const float*)d_in[12];
    const float* conv2d_b  = (const float*)d_in[13];
    float* outp = (float*)d_out;

    float *p_hn, *p_xz, *p_xc, *p_xdb, *p_h;
    cudaGetSymbolAddress((void**)&p_hn,  g_hn);
    cudaGetSymbolAddress((void**)&p_xz,  g_xz);
    cudaGetSymbolAddress((void**)&p_xc,  g_xc);
    cudaGetSymbolAddress((void**)&p_xdb, g_xdb);
    cudaGetSymbolAddress((void**)&p_h,   g_h);

    wconv_T<<<(9 * 60 * 60 + 255) / 256, 256>>>(conv2d_w);

    const float* hin = x;
    for (int layer = 0; layer < 2; layer++) {
        ln_kernel<<<BLR / 8, 256>>>(hin, ln_w + layer * DM, ln_b + layer * DM);
        gemm64<<<dim3(BLR / 64, 4), 256>>>(p_hn, in_proj_w + layer * 2 * DI * DM,
                                           p_xz, 2 * DI, DM);
        conv1d_silu<<<(BLR * DI + 255) / 256, 256>>>(conv_w + layer * DI * 4,
                                                     conv_b + layer * DI);
        gemm64<<<dim3(BLR / 64, 1), 256>>>(p_xc, x_proj_w + layer * 36 * DI,
                                           p_xdb, 36, DI);
        delta_kernel<<<(BLR * DI + 255) / 256, 256>>>(dt_proj_w + layer * DI * 4,
                                                      dt_proj_b + layer * DI);
        scan_phase1<<<dim3(120, NCH), 32>>>(A_log + layer * DI * DS);
        scan_phase2<<<15, 256>>>();
        scan_phase3<<<dim3(120, NCH), 32>>>(A_log + layer * DI * DS);
        gemm_out_gated<<<BLR / 64, 256>>>(out_proj_w + layer * DM * DI,
                                          Dv + layer * DI);
        hin = p_h;
    }
    conv2d_res<<<BLR / 64, 256>>>(conv2d_b, x, outp);
}

// round 4
// speedup vs baseline: 1.3304x; 1.3304x over previous
#include <cuda_runtime.h>

#define BATCH 2
#define LSEQ  16384
#define BLR   (BATCH*LSEQ)   // 32768 rows
#define DM    60
#define DI    120
#define DS    16
#define NCH   64             // scan chunks
#define SCH   (LSEQ/NCH)     // 256 steps per chunk

// ------------------------- scratch -------------------------
__device__ float g_hn[BLR*DM];
__device__ float g_xz[BLR*2*DI];
__device__ float g_xc[BLR*DI];
__device__ float g_xdb[BLR*36];
__device__ float g_delta[BLR*DI];
__device__ float g_u[BLR*DI];
__device__ float g_y[BLR*DI];
__device__ float g_h[BLR*DM];
__device__ float g_P [NCH*BATCH*DI*DS];
__device__ float g_Hc[NCH*BATCH*DI*DS];
__device__ float g_hinit[NCH*BATCH*DI*DS];
// transposed weights: WT[k][n]
__device__ float g_wt_in [2*DM*2*DI];   // [60][240] per layer
__device__ float g_wt_xp [2*DI*36];     // [120][36]
__device__ float g_wt_out[2*DI*DM];     // [120][60]
__device__ float g_wT    [9*DM*DM];     // [tap][ci][co]

__device__ __forceinline__ float siluf(float x) { return x / (1.f + __expf(-x)); }

// ------------------------- weight prep (transposes) -------------------------
__global__ void prep_weights(const float* __restrict__ in_w, const float* __restrict__ xp_w,
                             const float* __restrict__ out_w, const float* __restrict__ c2w) {
    int t = blockIdx.y;
    int i = blockIdx.x * 256 + threadIdx.x;
    if (t < 2) {                       // in_proj: [240][60] -> [60][240]
        if (i < 240 * 60) {
            int n = i / 60, k = i - n * 60;
            g_wt_in[t * 60 * 240 + k * 240 + n] = in_w[t * 240 * 60 + n * 60 + k];
        }
    } else if (t < 4) {                // x_proj: [36][120] -> [120][36]
        int l = t - 2;
        if (i < 36 * 120) {
            int n = i / 120, k = i - n * 120;
            g_wt_xp[l * 120 * 36 + k * 36 + n] = xp_w[l * 36 * 120 + n * 120 + k];
        }
    } else if (t < 6) {                // out_proj: [60][120] -> [120][60]
        int l = t - 4;
        if (i < 60 * 120) {
            int n = i / 120, k = i - n * 120;
            g_wt_out[l * 120 * 60 + k * 60 + n] = out_w[l * 60 * 120 + n * 120 + k];
        }
    } else {                           // conv2d: [co][ci][9] -> [tap][ci][co]
        if (i < 9 * 60 * 60) {
            int tap = i / 3600;
            int r = i - tap * 3600;
            int ci = r / 60, co = r - ci * 60;
            g_wT[i] = c2w[(co * 60 + ci) * 9 + tap];
        }
    }
}

// ------------------------- LayerNorm (one warp per row) -------------------------
__global__ void ln_kernel(const float* __restrict__ in, const float* __restrict__ w,
                          const float* __restrict__ b) {
    int row  = blockIdx.x * 8 + (threadIdx.x >> 5);
    int lane = threadIdx.x & 31;
    const float* r = in + (size_t)row * DM;
    float v0 = r[lane];
    float v1 = (lane + 32 < DM) ? r[lane + 32] : 0.f;
    float s = v0 + v1;
#pragma unroll
    for (int o = 16; o; o >>= 1) s += __shfl_xor_sync(0xffffffffu, s, o);
    float mu = s * (1.f / DM);
    float d0 = v0 - mu;
    float d1 = (lane + 32 < DM) ? (v1 - mu) : 0.f;
    float q = d0 * d0 + d1 * d1;
#pragma unroll
    for (int o = 16; o; o >>= 1) q += __shfl_xor_sync(0xffffffffu, q, o);
    float rstd = rsqrtf(q * (1.f / DM) + 1e-5f);
    float* op = g_hn + (size_t)row * DM;
    op[lane] = d0 * rstd * w[lane] + b[lane];
    if (lane + 32 < DM) op[lane + 32] = d1 * rstd * w[lane + 32] + b[lane + 32];
}

// ------------------------- GEMM: C[m,n] = sum_k A[m,k]*WT[k,n] -------------------------
// 64x64 tile, K multiple of 60, conflict-free smem, 4x4 microtile
__global__ __launch_bounds__(256) void gemm64T(const float* __restrict__ A,
                                               const float* __restrict__ WT,
                                               float* __restrict__ C, int N, int K) {
    __shared__ float Asr[64][60];
    __shared__ float Ws[60][64];
    int m0 = blockIdx.x * 64;
    int n0 = blockIdx.y * 64;
    int tid = threadIdx.x;
    int r0 = (tid >> 4) * 4;
    int c0 = (tid & 15) * 4;
    float acc[4][4];
#pragma unroll
    for (int i = 0; i < 4; i++)
#pragma unroll
        for (int j = 0; j < 4; j++) acc[i][j] = 0.f;

    for (int kc = 0; kc < K; kc += 60) {
#pragma unroll
        for (int i = tid; i < 64 * 60; i += 256) {
            int r = i / 60, k = i - r * 60;
            Asr[r][k] = A[(size_t)(m0 + r) * K + kc + k];
        }
#pragma unroll
        for (int i = tid; i < 60 * 64; i += 256) {
            int k = i >> 6, n = i & 63;
            int nn = n0 + n;
            Ws[k][n] = (nn < N) ? WT[(size_t)(kc + k) * N + nn] : 0.f;
        }
        __syncthreads();
#pragma unroll
        for (int k = 0; k < 60; k++) {
            float4 w4 = *(const float4*)&Ws[k][c0];
            float a0 = Asr[r0 + 0][k], a1 = Asr[r0 + 1][k];
            float a2 = Asr[r0 + 2][k], a3 = Asr[r0 + 3][k];
            acc[0][0] = fmaf(a0, w4.x, acc[0][0]); acc[0][1] = fmaf(a0, w4.y, acc[0][1]);
            acc[0][2] = fmaf(a0, w4.z, acc[0][2]); acc[0][3] = fmaf(a0, w4.w, acc[0][3]);
            acc[1][0] = fmaf(a1, w4.x, acc[1][0]); acc[1][1] = fmaf(a1, w4.y, acc[1][1]);
            acc[1][2] = fmaf(a1, w4.z, acc[1][2]); acc[1][3] = fmaf(a1, w4.w, acc[1][3]);
            acc[2][0] = fmaf(a2, w4.x, acc[2][0]); acc[2][1] = fmaf(a2, w4.y, acc[2][1]);
            acc[2][2] = fmaf(a2, w4.z, acc[2][2]); acc[2][3] = fmaf(a2, w4.w, acc[2][3]);
            acc[3][0] = fmaf(a3, w4.x, acc[3][0]); acc[3][1] = fmaf(a3, w4.y, acc[3][1]);
            acc[3][2] = fmaf(a3, w4.z, acc[3][2]); acc[3][3] = fmaf(a3, w4.w, acc[3][3]);
        }
        __syncthreads();
    }
#pragma unroll
    for (int i = 0; i < 4; i++) {
        int m = m0 + r0 + i;
#pragma unroll
        for (int j = 0; j < 4; j++) {
            int n = n0 + c0 + j;
            if (n < N) C[(size_t)m * N + n] = acc[i][j];
        }
    }
}

// ------------------------- causal depthwise conv1d (k=4) + bias + SiLU, x4 vec ----
__global__ void conv1d_silu(const float* __restrict__ cw, const float* __restrict__ cb) {
    int idx = blockIdx.x * 256 + threadIdx.x;
    if (idx >= BLR * (DI / 4)) return;
    int m = idx / (DI / 4);
    int d = (idx - m * (DI / 4)) * 4;
    int l = m & (LSEQ - 1);
    const float4* base = (const float4*)(g_xz + (size_t)m * (2 * DI) + d);
    float4 zero = make_float4(0.f, 0.f, 0.f, 0.f);
    float4 x0 = __ldg(base);
    float4 x1 = (l >= 1) ? __ldg(base - (2 * DI) / 4) : zero;
    float4 x2 = (l >= 2) ? __ldg(base - 2 * (2 * DI) / 4) : zero;
    float4 x3 = (l >= 3) ? __ldg(base - 3 * (2 * DI) / 4) : zero;
    float4 wa = __ldg((const float4*)(cw + (d + 0) * 4));
    float4 wb = __ldg((const float4*)(cw + (d + 1) * 4));
    float4 wc = __ldg((const float4*)(cw + (d + 2) * 4));
    float4 wd = __ldg((const float4*)(cw + (d + 3) * 4));
    float4 bb = __ldg((const float4*)(cb + d));
    float4 o;
    o.x = siluf(bb.x + x0.x * wa.w + x1.x * wa.z + x2.x * wa.y + x3.x * wa.x);
    o.y = siluf(bb.y + x0.y * wb.w + x1.y * wb.z + x2.y * wb.y + x3.y * wb.x);
    o.z = siluf(bb.z + x0.z * wc.w + x1.z * wc.z + x2.z * wc.y + x3.z * wc.x);
    o.w = siluf(bb.w + x0.w * wd.w + x1.w * wd.z + x2.w * wd.y + x3.w * wd.x);
    *(float4*)(g_xc + (size_t)m * DI + d) = o;
}

// ------------------------- delta = softplus(dt@dtw^T + dtb); u = delta*xc, x4 vec ----
__global__ void delta_kernel(const float* __restrict__ dtw, const float* __restrict__ dtb) {
    int idx = blockIdx.x * 256 + threadIdx.x;
    if (idx >= BLR * (DI / 4)) return;
    int m = idx / (DI / 4);
    int d = (idx - m * (DI / 4)) * 4;
    float4 xr = __ldg((const float4*)(g_xdb + (size_t)m * 36));
    float4 w0 = __ldg((const float4*)(dtw + (d + 0) * 4));
    float4 w1 = __ldg((const float4*)(dtw + (d + 1) * 4));
    float4 w2 = __ldg((const float4*)(dtw + (d + 2) * 4));
    float4 w3 = __ldg((const float4*)(dtw + (d + 3) * 4));
    float4 bb = __ldg((const float4*)(dtb + d));
    float s0 = bb.x + xr.x * w0.x + xr.y * w0.y + xr.z * w0.z + xr.w * w0.w;
    float s1 = bb.y + xr.x * w1.x + xr.y * w1.y + xr.z * w1.z + xr.w * w1.w;
    float s2 = bb.z + xr.x * w2.x + xr.y * w2.y + xr.z * w2.z + xr.w * w2.w;
    float s3 = bb.w + xr.x * w3.x + xr.y * w3.y + xr.z * w3.z + xr.w * w3.w;
    float4 dl;
    dl.x = (s0 > 20.f) ? s0 : log1pf(__expf(s0));
    dl.y = (s1 > 20.f) ? s1 : log1pf(__expf(s1));
    dl.z = (s2 > 20.f) ? s2 : log1pf(__expf(s2));
    dl.w = (s3 > 20.f) ? s3 : log1pf(__expf(s3));
    float4 xc = __ldg((const float4*)(g_xc + (size_t)m * DI + d));
    float4 uu = make_float4(dl.x * xc.x, dl.y * xc.y, dl.z * xc.z, dl.w * xc.w);
    *(float4*)(g_delta + (size_t)m * DI + d) = dl;
    *(float4*)(g_u + (size_t)m * DI + d) = uu;
}

// ------------------------- chunked selective scan -------------------------
// warp layout: 8 channels (dl = lane>>2) x 4 states per thread (n0 = (lane&3)*4)
__global__ __launch_bounds__(128) void scan_phase1(const float* __restrict__ A_log) {
    int w = blockIdx.x * 4 + (threadIdx.x >> 5);
    int lane = threadIdx.x & 31;
    int c = w & (NCH - 1);
    int rem = w >> 6;
    int o8 = rem % 15;
    int b = rem / 15;
    int d = o8 * 8 + (lane >> 2);
    int n0 = (lane & 3) * 4;
    float4 Al = __ldg((const float4*)(A_log + d * DS + n0));
    float An0 = -__expf(Al.x), An1 = -__expf(Al.y), An2 = -__expf(Al.z), An3 = -__expf(Al.w);
    size_t rbase = ((size_t)b * LSEQ + c * SCH);
    const float* dp = g_delta + rbase * DI + d;
    const float* up = g_u + rbase * DI + d;
    const float4* bp = (const float4*)(g_xdb + rbase * 36 + 4 + n0);
    float h0 = 0.f, h1 = 0.f, h2 = 0.f, h3 = 0.f;
    float P0 = 1.f, P1 = 1.f, P2 = 1.f, P3 = 1.f;
#pragma unroll 4
    for (int t = 0; t < SCH; t++) {
        float dlt = __ldg(dp);
        float uu = __ldg(up);
        float4 B4 = __ldg(bp);
        float e0 = __expf(dlt * An0), e1 = __expf(dlt * An1);
        float e2 = __expf(dlt * An2), e3 = __expf(dlt * An3);
        h0 = fmaf(e0, h0, uu * B4.x); P0 *= e0;
        h1 = fmaf(e1, h1, uu * B4.y); P1 *= e1;
        h2 = fmaf(e2, h2, uu * B4.z); P2 *= e2;
        h3 = fmaf(e3, h3, uu * B4.w); P3 *= e3;
        dp += DI; up += DI; bp += 9;
    }
    int o = ((c * BATCH + b) * DI + d) * DS + n0;
    *(float4*)(g_Hc + o) = make_float4(h0, h1, h2, h3);
    *(float4*)(g_P + o)  = make_float4(P0, P1, P2, P3);
}

__global__ void scan_phase2() {
    int tid = blockIdx.x * 256 + threadIdx.x;
    if (tid >= BATCH * DI * DS) return;
    float h = 0.f;
#pragma unroll
    for (int c = 0; c < NCH; c++) {
        int o = c * (BATCH * DI * DS) + tid;
        g_hinit[o] = h;
        h = fmaf(g_P[o], h, g_Hc[o]);
    }
}

__global__ __launch_bounds__(128) void scan_phase3(const float* __restrict__ A_log) {
    int w = blockIdx.x * 4 + (threadIdx.x >> 5);
    int lane = threadIdx.x & 31;
    int c = w & (NCH - 1);
    int rem = w >> 6;
    int o8 = rem % 15;
    int b = rem / 15;
    int d = o8 * 8 + (lane >> 2);
    int q = lane & 3;
    int n0 = q * 4;
    float4 Al = __ldg((const float4*)(A_log + d * DS + n0));
    float An0 = -__expf(Al.x), An1 = -__expf(Al.y), An2 = -__expf(Al.z), An3 = -__expf(Al.w);
    size_t rbase = ((size_t)b * LSEQ + c * SCH);
    const float* dp = g_delta + rbase * DI + d;
    const float* up = g_u + rbase * DI + d;
    const float4* bp = (const float4*)(g_xdb + rbase * 36 + 4 + n0);
    const float4* cp = (const float4*)(g_xdb + rbase * 36 + 20 + n0);
    float* yp = g_y + rbase * DI + d;
    int o = ((c * BATCH + b) * DI + d) * DS + n0;
    float4 hi = *(const float4*)(g_hinit + o);
    float h0 = hi.x, h1 = hi.y, h2 = hi.z, h3 = hi.w;
#pragma unroll 4
    for (int t = 0; t < SCH; t++) {
        float dlt = __ldg(dp);
        float uu = __ldg(up);
        float4 B4 = __ldg(bp);
        float4 C4 = __ldg(cp);
        float e0 = __expf(dlt * An0), e1 = __expf(dlt * An1);
        float e2 = __expf(dlt * An2), e3 = __expf(dlt * An3);
        h0 = fmaf(e0, h0, uu * B4.x);
        h1 = fmaf(e1, h1, uu * B4.y);
        h2 = fmaf(e2, h2, uu * B4.z);
        h3 = fmaf(e3, h3, uu * B4.w);
        float s = h0 * C4.x + h1 * C4.y + h2 * C4.z + h3 * C4.w;
        s += __shfl_xor_sync(0xffffffffu, s, 1);
        s += __shfl_xor_sync(0xffffffffu, s, 2);
        if (q == 0) yp[0] = s;
        dp += DI; up += DI; bp += 9; cp += 9; yp += DI;
    }
}

// ------------------------- out_proj with fused gating: A = (y + D*xc)*silu(z) -------
__global__ __launch_bounds__(256) void gemm_out_gated(const float* __restrict__ WT,
                                                      const float* __restrict__ Dvec) {
    __shared__ float Asr[64][60];
    __shared__ float Ws[60][64];
    int m0 = blockIdx.x * 64;
    int tid = threadIdx.x;
    int r0 = (tid >> 4) * 4;
    int c0 = (tid & 15) * 4;
    float acc[4][4];
#pragma unroll
    for (int i = 0; i < 4; i++)
#pragma unroll
        for (int j = 0; j < 4; j++) acc[i][j] = 0.f;

    for (int kc = 0; kc < DI; kc += 60) {
#pragma unroll
        for (int i = tid; i < 64 * 60; i += 256) {
            int r = i / 60, k = i - r * 60;
            int m = m0 + r;
            int e = kc + k;
            float yv = g_y[(size_t)m * DI + e];
            float xcv = g_xc[(size_t)m * DI + e];
            float zv = g_xz[(size_t)m * (2 * DI) + DI + e];
            Asr[r][k] = (yv + __ldg(Dvec + e) * xcv) * siluf(zv);
        }
#pragma unroll
        for (int i = tid; i < 60 * 64; i += 256) {
            int k = i >> 6, n = i & 63;
            Ws[k][n] = (n < DM) ? WT[(size_t)(kc + k) * DM + n] : 0.f;
        }
        __syncthreads();
#pragma unroll
        for (int k = 0; k < 60; k++) {
            float4 w4 = *(const float4*)&Ws[k][c0];
            float a0 = Asr[r0 + 0][k], a1 = Asr[r0 + 1][k];
            float a2 = Asr[r0 + 2][k], a3 = Asr[r0 + 3][k];
            acc[0][0] = fmaf(a0, w4.x, acc[0][0]); acc[0][1] = fmaf(a0, w4.y, acc[0][1]);
            acc[0][2] = fmaf(a0, w4.z, acc[0][2]); acc[0][3] = fmaf(a0, w4.w, acc[0][3]);
            acc[1][0] = fmaf(a1, w4.x, acc[1][0]); acc[1][1] = fmaf(a1, w4.y, acc[1][1]);
            acc[1][2] = fmaf(a1, w4.z, acc[1][2]); acc[1][3] = fmaf(a1, w4.w, acc[1][3]);
            acc[2][0] = fmaf(a2, w4.x, acc[2][0]); acc[2][1] = fmaf(a2, w4.y, acc[2][1]);
            acc[2][2] = fmaf(a2, w4.z, acc[2][2]); acc[2][3] = fmaf(a2, w4.w, acc[2][3]);
            acc[3][0] = fmaf(a3, w4.x, acc[3][0]); acc[3][1] = fmaf(a3, w4.y, acc[3][1]);
            acc[3][2] = fmaf(a3, w4.z, acc[3][2]); acc[3][3] = fmaf(a3, w4.w, acc[3][3]);
        }
        __syncthreads();
    }
#pragma unroll
    for (int i = 0; i < 4; i++) {
        int m = m0 + r0 + i;
#pragma unroll
        for (int j = 0; j < 4; j++) {
            int n = c0 + j;
            if (n < DM) g_h[(size_t)m * DM + n] = acc[i][j];
        }
    }
}

// ------------------------- 3x3 conv2d (implicit GEMM) + bias + residual -------------
__global__ __launch_bounds__(256) void conv2d_res(const float* __restrict__ bias,
                                                  const float* __restrict__ x0,
                                                  float* __restrict__ outp) {
    __shared__ float Asr[64][60];
    __shared__ float Ws[60][64];
    int p0 = blockIdx.x * 64;
    int tid = threadIdx.x;
    int r0 = (tid >> 4) * 4;
    int c0 = (tid & 15) * 4;
    float acc[4][4];
#pragma unroll
    for (int i = 0; i < 4; i++)
#pragma unroll
        for (int j = 0; j < 4; j++) acc[i][j] = 0.f;

    for (int tap = 0; tap < 9; tap++) {
        int dy = tap / 3 - 1, dx = tap % 3 - 1;
#pragma unroll
        for (int i = tid; i < 64 * 60; i += 256) {
            int r = i / 60, ci = i - r * 60;
            int p = p0 + r;
            int l = p & (LSEQ - 1);
            int bI = p >> 14;
            int yy = l >> 7, xx = l & 127;
            int sy = yy + dy, sx = xx + dx;
            float v = 0.f;
            if ((unsigned)sy < 128u && (unsigned)sx < 128u)
                v = g_h[(size_t)((bI << 14) + (sy << 7) + sx) * DM + ci];
            Asr[r][ci] = v;
        }
#pragma unroll
        for (int i = tid; i < 60 * 64; i += 256) {
            int k = i >> 6, nn = i & 63;
            Ws[k][nn] = (nn < DM) ? g_wT[tap * 3600 + k * 60 + nn] : 0.f;
        }
        __syncthreads();
#pragma unroll
        for (int k = 0; k < 60; k++) {
            float4 w4 = *(const float4*)&Ws[k][c0];
            float a0 = Asr[r0 + 0][k], a1 = Asr[r0 + 1][k];
            float a2 = Asr[r0 + 2][k], a3 = Asr[r0 + 3][k];
            acc[0][0] = fmaf(a0, w4.x, acc[0][0]); acc[0][1] = fmaf(a0, w4.y, acc[0][1]);
            acc[0][2] = fmaf(a0, w4.z, acc[0][2]); acc[0][3] = fmaf(a0, w4.w, acc[0][3]);
            acc[1][0] = fmaf(a1, w4.x, acc[1][0]); acc[1][1] = fmaf(a1, w4.y, acc[1][1]);
            acc[1][2] = fmaf(a1, w4.z, acc[1][2]); acc[1][3] = fmaf(a1, w4.w, acc[1][3]);
            acc[2][0] = fmaf(a2, w4.x, acc[2][0]); acc[2][1] = fmaf(a2, w4.y, acc[2][1]);
            acc[2][2] = fmaf(a2, w4.z, acc[2][2]); acc[2][3] = fmaf(a2, w4.w, acc[2][3]);
            acc[3][0] = fmaf(a3, w4.x, acc[3][0]); acc[3][1] = fmaf(a3, w4.y, acc[3][1]);
            acc[3][2] = fmaf(a3, w4.z, acc[3][2]); acc[3][3] = fmaf(a3, w4.w, acc[3][3]);
        }
        __syncthreads();
    }
#pragma unroll
    for (int i = 0; i < 4; i++) {
        int p = p0 + r0 + i;
#pragma unroll
        for (int j = 0; j < 4; j++) {
            int co = c0 + j;
            if (co < DM)
                outp[(size_t)p * DM + co] = acc[i][j] + bias[co] + x0[(size_t)p * DM + co];
        }
    }
}

// ------------------------- launch -------------------------
extern "C" void kernel_launch(void* const* d_in, const int* in_sizes, int n_in,
                              void* d_out, int out_size) {
    (void)in_sizes; (void)n_in; (void)out_size;
    const float* x         = (const float*)d_in[0];
    const float* ln_w      = (const float*)d_in[1];
    const float* ln_b      = (const float*)d_in[2];
    const float* in_proj_w = (const float*)d_in[3];
    const float* conv_w    = (const float*)d_in[4];
    const float* conv_b    = (const float*)d_in[5];
    const float* x_proj_w  = (const float*)d_in[6];
    const float* dt_proj_w = (const float*)d_in[7];
    const float* dt_proj_b = (const float*)d_in[8];
    const float* A_log     = (const float*)d_in[9];
    const float* Dv        = (const float*)d_in[10];
    const float* out_proj_w= (const float*)d_in[11];
    const float* conv2d_w  = (const float*)d_in[12];
    const float* conv2d_b  = (const float*)d_in[13];
    float* outp = (float*)d_out;

    float *p_hn, *p_xz, *p_xc, *p_xdb, *p_h, *p_wti, *p_wtx, *p_wto;
    cudaGetSymbolAddress((void**)&p_hn,  g_hn);
    cudaGetSymbolAddress((void**)&p_xz,  g_xz);
    cudaGetSymbolAddress((void**)&p_xc,  g_xc);
    cudaGetSymbolAddress((void**)&p_xdb, g_xdb);
    cudaGetSymbolAddress((void**)&p_h,   g_h);
    cudaGetSymbolAddress((void**)&p_wti, g_wt_in);
    cudaGetSymbolAddress((void**)&p_wtx, g_wt_xp);
    cudaGetSymbolAddress((void**)&p_wto, g_wt_out);

    prep_weights<<<dim3(132, 7), 256>>>(in_proj_w, x_proj_w, out_proj_w, conv2d_w);

    const float* hin = x;
    for (int layer = 0; layer < 2; layer++) {
        ln_kernel<<<BLR / 8, 256>>>(hin, ln_w + layer * DM, ln_b + layer * DM);
        gemm64T<<<dim3(BLR / 64, 4), 256>>>(p_hn, p_wti + layer * 60 * 240,
                                            p_xz, 2 * DI, DM);
        conv1d_silu<<<(BLR * (DI / 4) + 255) / 256, 256>>>(conv_w + layer * DI * 4,
                                                           conv_b + layer * DI);
        gemm64T<<<dim3(BLR / 64, 1), 256>>>(p_xc, p_wtx + layer * 120 * 36,
                                            p_xdb, 36, DI);
        delta_kernel<<<(BLR * (DI / 4) + 255) / 256, 256>>>(dt_proj_w + layer * DI * 4,
                                                            dt_proj_b + layer * DI);
        scan_phase1<<<1920 / 4, 128>>>(A_log + layer * DI * DS);
        scan_phase2<<<15, 256>>>();
        scan_phase3<<<1920 / 4, 128>>>(A_log + layer * DI * DS);
        gemm_out_gated<<<BLR / 64, 256>>>(p_wto + layer * 120 * 60, Dv + layer * DI);
        hin = p_h;
    }
    conv2d_res<<<BLR / 64, 256>>>(conv2d_b, x, outp);
}